// round 15
// baseline (speedup 1.0000x reference)
#include <cuda_runtime.h>
#include <cuda_fp16.h>
#include <cstdint>
#include <math.h>

// ---------------------------------------------------------------------------
// SelfAttentionV3 (B=4, S=2048, E=1024) via fp16 hi-only HMMA GEMMs.
// R15: R14 tile (128x128 CTA, 32x64 warp) + Kc=64 (half the barriers, 4 k16
// steps per sync), 3-stage 96KB pipeline, register-lean cp.async addressing.
// ---------------------------------------------------------------------------

#define EMBED 1024
#define BATCH 4
#define SEQ   2048
#define ROWS  (BATCH * SEQ)   // 8192

typedef __half h16;

// ---------------- static scratch (no allocs allowed) -----------------------
__device__ h16 g_Xhi[(size_t)ROWS * EMBED];
__device__ h16 g_Wqkvhi[(size_t)3 * EMBED * EMBED];
__device__ h16 g_Wouthi[(size_t)EMBED * EMBED];
__device__ h16 g_qkvhi[(size_t)ROWS * 3 * EMBED];
__device__ h16 g_att[(size_t)BATCH * SEQ * SEQ];    // logits, then probs (in-place)
__device__ h16 g_vthi[(size_t)BATCH * EMBED * SEQ];
__device__ h16 g_ctxhi[(size_t)ROWS * EMBED];

// ---------------- PTX helpers ----------------------------------------------
__device__ __forceinline__ uint32_t smem_u32(const void* p) {
    uint32_t a;
    asm("{ .reg .u64 t; cvta.to.shared.u64 t, %1; cvt.u32.u64 %0, t; }"
        : "=r"(a) : "l"(p));
    return a;
}
__device__ __forceinline__ void cp16(uint32_t dst, const void* src) {
    asm volatile("cp.async.cg.shared.global [%0], [%1], 16;"
                 :: "r"(dst), "l"(src) : "memory");
}
__device__ __forceinline__ void cp_commit() {
    asm volatile("cp.async.commit_group;" ::: "memory");
}
template <int N>
__device__ __forceinline__ void cp_wait() {
    asm volatile("cp.async.wait_group %0;" :: "n"(N) : "memory");
}
__device__ __forceinline__ void ldm4(uint32_t* r, uint32_t addr) {
    asm volatile("ldmatrix.sync.aligned.m8n8.x4.shared.b16 {%0,%1,%2,%3}, [%4];"
                 : "=r"(r[0]), "=r"(r[1]), "=r"(r[2]), "=r"(r[3]) : "r"(addr));
}
__device__ __forceinline__ void mma16816(float* c, const uint32_t* a, const uint32_t* b) {
    asm volatile("mma.sync.aligned.m16n8k16.row.col.f32.f16.f16.f32 "
                 "{%0,%1,%2,%3}, {%4,%5,%6,%7}, {%8,%9}, {%0,%1,%2,%3};"
                 : "+f"(c[0]), "+f"(c[1]), "+f"(c[2]), "+f"(c[3])
                 : "r"(a[0]), "r"(a[1]), "r"(a[2]), "r"(a[3]), "r"(b[0]), "r"(b[1]));
}
__device__ __forceinline__ uint32_t pack2(h16 a, h16 b) {
    uint16_t ua = *reinterpret_cast<uint16_t*>(&a);
    uint16_t ub = *reinterpret_cast<uint16_t*>(&b);
    return (uint32_t)ua | ((uint32_t)ub << 16);
}

// ---------------------------------------------------------------------------
// fp16 GEMM: C = scale*(A[M,K] x B[N,K]^T) (+bias). CTA tile 128x128, Kc=64.
// A/B smem row (128B): 64 fp16, XOR-(row&7)*16 swizzle (classic SW128).
// 8 warps in 4(m) x 2(n) grid, warp tile 32x64.
// OUT: 0 = fp32 C, 2 = fp16 Chi.
// ---------------------------------------------------------------------------
#define BM 128
#define BN 128
#define NSTAGE 3
#define A_BYTES 16384                    // 128 rows x 128B
#define B_BYTES 16384                    // 128 rows x 128B
#define STAGE_BYTES (A_BYTES + B_BYTES)  // 32768
#define SMEM_TOTAL (NSTAGE * STAGE_BYTES)  // 98304

template <bool HAS_BIAS, int OUT>
__global__ __launch_bounds__(256, 2) void gemm_fp16(
    const h16* __restrict__ Ah, const h16* __restrict__ Bh,
    const float* __restrict__ bias,
    float* __restrict__ C, h16* __restrict__ Chi,
    int K, int lda, int ldb, int ldc,
    long aBS, long bBS, long cBS, float scale)
{
    extern __shared__ char smem[];
    const uint32_t sb = smem_u32(smem);
    const int tid = threadIdx.x;
    const int lane = tid & 31;
    const int wid = tid >> 5;
    const int wm = wid & 3;       // m 32-quarter (0..3)
    const int wn = wid >> 2;      // n 64-half    (0..1)

    const long bm = (long)blockIdx.y * BM;
    const long bn = (long)blockIdx.x * BN;
    Ah += (long)blockIdx.z * aBS;
    Bh += (long)blockIdx.z * bBS;
    if (OUT == 0) C   += (long)blockIdx.z * cBS;
    else          Chi += (long)blockIdx.z * cBS;

    const int nchunk = K >> 6;           // 64-K chunks

    // ---- cp.async assignments: 4 A + 4 B 16B chunks per thread ----
    // row pattern per i: row = row0 + 32*i  (low 3 bits constant -> same sw)
    const int row0 = tid >> 3;           // 0..31
    const int qq = tid & 7;              // 16B unit in 128B row
    const uint32_t dst0 = (uint32_t)(row0 * 128) +
                          ((uint32_t)(qq * 16) ^ ((row0 & 7) * 16));
    const h16* pA0 = Ah + (size_t)(bm + row0) * lda + qq * 8;
    const h16* pB0 = Bh + (size_t)(bn + row0) * ldb + qq * 8;

    // ---- ldmatrix lane address components ----
    const int rA = (lane & 7) + ((lane >> 3) & 1) * 8;
    const uint32_t cA16 = ((lane >> 4) & 1) * 16;
    const int rB = (lane & 7) + ((lane >> 4) & 1) * 8;
    const uint32_t cB16 = ((lane >> 3) & 1) * 16;

    uint32_t aoff[2], axor[2];
#pragma unroll
    for (int mt = 0; mt < 2; mt++) {
        int arow = wm * 32 + mt * 16 + rA;
        aoff[mt] = arow * 128;
        axor[mt] = (arow & 7) * 16;
    }
    uint32_t boff[4], bxor[4];
#pragma unroll
    for (int t = 0; t < 4; t++) {
        int brow = wn * 64 + t * 16 + rB;
        boff[t] = brow * 128;
        bxor[t] = (brow & 7) * 16;
    }

    float acc[2][8][4];
#pragma unroll
    for (int mt = 0; mt < 2; mt++)
#pragma unroll
        for (int nt = 0; nt < 8; nt++)
#pragma unroll
            for (int r = 0; r < 4; r++) acc[mt][nt][r] = 0.f;

    // ---- prologue: stages 0..NSTAGE-2 in flight ----
#pragma unroll
    for (int st = 0; st < NSTAGE - 1; st++) {
        int k0 = st * 64;
        uint32_t base = sb + st * STAGE_BYTES;
#pragma unroll
        for (int i = 0; i < 4; i++) {
            cp16(base + dst0 + i * 4096, pA0 + (long)(i * 32) * lda + k0);
            cp16(base + A_BYTES + dst0 + i * 4096, pB0 + (long)(i * 32) * ldb + k0);
        }
        cp_commit();
    }
    cp_wait<NSTAGE - 2>();
    __syncthreads();

    // ---- main loop: ONE barrier per 64-K chunk ----
    for (int kc = 0; kc < nchunk; kc++) {
        const uint32_t baseA = sb + (kc % NSTAGE) * STAGE_BYTES;
        const uint32_t baseB = baseA + A_BYTES;

        // prefetch chunk kc+NSTAGE-1 into the stage consumed at kc-1
        int next = kc + NSTAGE - 1;
        if (next < nchunk) {
            int k0 = next * 64;
            uint32_t nb = sb + (next % NSTAGE) * STAGE_BYTES;
#pragma unroll
            for (int i = 0; i < 4; i++) {
                cp16(nb + dst0 + i * 4096, pA0 + (long)(i * 32) * lda + k0);
                cp16(nb + A_BYTES + dst0 + i * 4096, pB0 + (long)(i * 32) * ldb + k0);
            }
        }
        cp_commit();

        // compute current chunk: 4 k16 steps, 16 MMAs + 6 LDSM each
#pragma unroll
        for (int s = 0; s < 4; s++) {
            uint32_t bh[16];
#pragma unroll
            for (int t = 0; t < 4; t++) {
                uint32_t c = s * 32 + cB16;
                ldm4(&bh[t * 4], baseB + boff[t] + (c ^ bxor[t]));
            }
#pragma unroll
            for (int mt = 0; mt < 2; mt++) {
                uint32_t a[4];
                uint32_t cc = s * 32 + cA16;
                ldm4(a, baseA + aoff[mt] + (cc ^ axor[mt]));
#pragma unroll
                for (int nt = 0; nt < 8; nt++) mma16816(acc[mt][nt], a, &bh[nt * 2]);
            }
        }

        cp_wait<NSTAGE - 2>();   // chunk kc+1 resident
        __syncthreads();
    }

    // ---- epilogue ----
#pragma unroll
    for (int mt = 0; mt < 2; mt++) {
        long r0 = bm + wm * 32 + mt * 16 + (lane >> 2);
        long r1 = r0 + 8;
#pragma unroll
        for (int nt = 0; nt < 8; nt++) {
            long col = bn + wn * 64 + nt * 8 + (lane & 3) * 2;
            float b0v = 0.f, b1v = 0.f;
            if (HAS_BIAS) { b0v = bias[col]; b1v = bias[col + 1]; }
            float v00 = acc[mt][nt][0] * scale + b0v;
            float v01 = acc[mt][nt][1] * scale + b1v;
            float v10 = acc[mt][nt][2] * scale + b0v;
            float v11 = acc[mt][nt][3] * scale + b1v;
            if (OUT == 2) {
                *reinterpret_cast<uint32_t*>(&Chi[r0 * ldc + col]) =
                    pack2(__float2half(v00), __float2half(v01));
                *reinterpret_cast<uint32_t*>(&Chi[r1 * ldc + col]) =
                    pack2(__float2half(v10), __float2half(v11));
            } else {
                float2 u0 = make_float2(v00, v01);
                float2 u1 = make_float2(v10, v11);
                *reinterpret_cast<float2*>(&C[r0 * ldc + col]) = u0;
                *reinterpret_cast<float2*>(&C[r1 * ldc + col]) = u1;
            }
        }
    }
}

// ---------------------------------------------------------------------------
// fp32 -> fp16 conversion (vectorized)
// ---------------------------------------------------------------------------
__global__ __launch_bounds__(256) void split_h_kernel(
    const float* __restrict__ src, h16* __restrict__ hi, int n4)
{
    int i = blockIdx.x * blockDim.x + threadIdx.x;
    if (i >= n4) return;
    float4 v = reinterpret_cast<const float4*>(src)[i];
    reinterpret_cast<uint2*>(hi)[i] = make_uint2(
        pack2(__float2half(v.x), __float2half(v.y)),
        pack2(__float2half(v.z), __float2half(v.w)));
}

// ---------------------------------------------------------------------------
// V transpose (hi only): vt[b][e][s] = qkv[b*S+s][2E+e]
// ---------------------------------------------------------------------------
__global__ __launch_bounds__(256) void transpose_v_kernel(
    const h16* __restrict__ qh, h16* __restrict__ vth)
{
    __shared__ h16 th[32][33];
    const int b = blockIdx.z;
    const int e0 = blockIdx.x * 32;
    const int s0 = blockIdx.y * 32;
    const int tx = threadIdx.x & 31;
    const int ty = threadIdx.x >> 5;  // 0..7
#pragma unroll
    for (int i = 0; i < 4; i++) {
        int s = s0 + ty + i * 8;
        size_t idx = (size_t)(b * SEQ + s) * (3 * EMBED) + 2 * EMBED + e0 + tx;
        th[ty + i * 8][tx] = qh[idx];
    }
    __syncthreads();
#pragma unroll
    for (int i = 0; i < 4; i++) {
        int e = e0 + ty + i * 8;
        size_t o = (size_t)(b * EMBED + e) * SEQ + s0 + tx;
        vth[o] = th[tx][ty + i * 8];
    }
}

// ---------------------------------------------------------------------------
// Row softmax with mask, IN-PLACE on fp16 logits (one block per row).
// ---------------------------------------------------------------------------
__global__ __launch_bounds__(256) void softmax_kernel(
    h16* __restrict__ att, const int* __restrict__ mask)
{
    const size_t row = blockIdx.x;
    h16* a = att + row * SEQ;
    const int* m = mask + row * SEQ;
    const int tid = threadIdx.x;

    __shared__ float red_max[8];
    __shared__ float red_sum[8];

    float v[8];
    float mx = -INFINITY;
#pragma unroll
    for (int i = 0; i < 8; i++) {
        int idx = tid + i * 256;
        float x = __half2float(a[idx]);
        x = (m[idx] != 0) ? x : -INFINITY;
        v[i] = x;
        mx = fmaxf(mx, x);
    }
#pragma unroll
    for (int o = 16; o > 0; o >>= 1)
        mx = fmaxf(mx, __shfl_xor_sync(0xffffffffu, mx, o));
    if ((tid & 31) == 0) red_max[tid >> 5] = mx;
    __syncthreads();
    float bmax = red_max[0];
#pragma unroll
    for (int w = 1; w < 8; w++) bmax = fmaxf(bmax, red_max[w]);

    float s = 0.f;
#pragma unroll
    for (int i = 0; i < 8; i++) {
        v[i] = __expf(v[i] - bmax);
        s += v[i];
    }
#pragma unroll
    for (int o = 16; o > 0; o >>= 1)
        s += __shfl_xor_sync(0xffffffffu, s, o);
    if ((tid & 31) == 0) red_sum[tid >> 5] = s;
    __syncthreads();
    float total = 0.f;
#pragma unroll
    for (int w = 0; w < 8; w++) total += red_sum[w];

    float inv = 1.f / total;
#pragma unroll
    for (int i = 0; i < 8; i++) {
        int idx = tid + i * 256;
        a[idx] = __float2half(v[i] * inv);
    }
}

// ---------------------------------------------------------------------------
extern "C" void kernel_launch(void* const* d_in, const int* in_sizes, int n_in,
                              void* d_out, int out_size)
{
    const float* X    = (const float*)d_in[0];
    const int*   mask = (const int*)  d_in[1];
    const float* Wqkv = (const float*)d_in[2];
    const float* bqkv = (const float*)d_in[3];
    const float* Wout = (const float*)d_in[4];
    const float* bout = (const float*)d_in[5];
    float* out = (float*)d_out;

    h16 *Xhi, *Wqkvhi, *Wouthi, *qkvhi, *att, *vthi, *ctxhi;
    cudaGetSymbolAddress((void**)&Xhi, g_Xhi);
    cudaGetSymbolAddress((void**)&Wqkvhi, g_Wqkvhi);
    cudaGetSymbolAddress((void**)&Wouthi, g_Wouthi);
    cudaGetSymbolAddress((void**)&qkvhi, g_qkvhi);
    cudaGetSymbolAddress((void**)&att, g_att);
    cudaGetSymbolAddress((void**)&vthi, g_vthi);
    cudaGetSymbolAddress((void**)&ctxhi, g_ctxhi);

    // NOTE: attributes must be set on the EXACT instantiations launched below.
    cudaFuncSetAttribute(gemm_fp16<true, 2>,
                         cudaFuncAttributeMaxDynamicSharedMemorySize, SMEM_TOTAL);
    cudaFuncSetAttribute(gemm_fp16<false, 2>,
                         cudaFuncAttributeMaxDynamicSharedMemorySize, SMEM_TOTAL);
    cudaFuncSetAttribute(gemm_fp16<true, 0>,
                         cudaFuncAttributeMaxDynamicSharedMemorySize, SMEM_TOTAL);

    // 0) convert inputs to fp16 (hi only)
    split_h_kernel<<<(ROWS * EMBED / 4 + 255) / 256, 256>>>(X, Xhi, ROWS * EMBED / 4);
    split_h_kernel<<<(3 * EMBED * EMBED / 4 + 255) / 256, 256>>>(
        Wqkv, Wqkvhi, 3 * EMBED * EMBED / 4);
    split_h_kernel<<<(EMBED * EMBED / 4 + 255) / 256, 256>>>(
        Wout, Wouthi, EMBED * EMBED / 4);

    // 1) qkv = X Wqkv^T + bqkv  (fp16 output)
    {
        dim3 grid(3 * EMBED / BN, ROWS / BM, 1);
        gemm_fp16<true, 2><<<grid, 256, SMEM_TOTAL>>>(
            Xhi, Wqkvhi, bqkv,
            nullptr, qkvhi,
            EMBED, EMBED, EMBED, 3 * EMBED,
            0, 0, 0, 1.0f);
    }
    // 2) vt = V^T
    {
        dim3 grid(EMBED / 32, SEQ / 32, BATCH);
        transpose_v_kernel<<<grid, 256>>>(qkvhi, vthi);
    }
    // 3) att = Q K^T / 32  (fp16 logits)
    {
        dim3 grid(SEQ / BN, SEQ / BM, BATCH);
        gemm_fp16<false, 2><<<grid, 256, SMEM_TOTAL>>>(
            qkvhi, qkvhi + EMBED, nullptr,
            nullptr, att,
            EMBED, 3 * EMBED, 3 * EMBED, SEQ,
            (long)SEQ * 3 * EMBED, (long)SEQ * 3 * EMBED, (long)SEQ * SEQ,
            1.0f / 32.0f);
    }
    // 4) softmax in-place on fp16 logits -> fp16 probs
    softmax_kernel<<<BATCH * SEQ, 256>>>(att, mask);

    // 5) ctx = p vt^T  (fp16 output)
    {
        dim3 grid(EMBED / BN, SEQ / BM, BATCH);
        gemm_fp16<false, 2><<<grid, 256, SMEM_TOTAL>>>(
            att, vthi, nullptr,
            nullptr, ctxhi,
            SEQ, SEQ, SEQ, EMBED,
            (long)SEQ * SEQ, (long)EMBED * SEQ, (long)SEQ * EMBED,
            1.0f);
    }
    // 6) out = ctx Wout^T + bout  (fp32)
    {
        dim3 grid(EMBED / BN, ROWS / BM, 1);
        gemm_fp16<true, 0><<<grid, 256, SMEM_TOTAL>>>(
            ctxhi, Wouthi, bout,
            out, nullptr,
            EMBED, EMBED, EMBED, EMBED,
            0, 0, 0, 1.0f);
    }
}

// round 16
// speedup vs baseline: 1.0283x; 1.0283x over previous
#include <cuda_runtime.h>
#include <cuda_fp16.h>
#include <cstdint>
#include <math.h>

// ---------------------------------------------------------------------------
// SelfAttentionV3 (B=4, S=2048, E=1024) via fp16 hi-only HMMA GEMMs.
// R16: revert to R14 config (128x128 CTA, 32x64 warp, Kc=32, 2 CTAs/SM --
// best measured: 437.3us), deepen pipeline to 6 stages (96KB/CTA), merge the
// three fp32->fp16 conversion launches into one.
// ---------------------------------------------------------------------------

#define EMBED 1024
#define BATCH 4
#define SEQ   2048
#define ROWS  (BATCH * SEQ)   // 8192

typedef __half h16;

// ---------------- static scratch (no allocs allowed) -----------------------
__device__ h16 g_Xhi[(size_t)ROWS * EMBED];
__device__ h16 g_Wqkvhi[(size_t)3 * EMBED * EMBED];
__device__ h16 g_Wouthi[(size_t)EMBED * EMBED];
__device__ h16 g_qkvhi[(size_t)ROWS * 3 * EMBED];
__device__ h16 g_att[(size_t)BATCH * SEQ * SEQ];    // logits, then probs (in-place)
__device__ h16 g_vthi[(size_t)BATCH * EMBED * SEQ];
__device__ h16 g_ctxhi[(size_t)ROWS * EMBED];

// ---------------- PTX helpers ----------------------------------------------
__device__ __forceinline__ uint32_t smem_u32(const void* p) {
    uint32_t a;
    asm("{ .reg .u64 t; cvta.to.shared.u64 t, %1; cvt.u32.u64 %0, t; }"
        : "=r"(a) : "l"(p));
    return a;
}
__device__ __forceinline__ void cp16(uint32_t dst, const void* src) {
    asm volatile("cp.async.cg.shared.global [%0], [%1], 16;"
                 :: "r"(dst), "l"(src) : "memory");
}
__device__ __forceinline__ void cp_commit() {
    asm volatile("cp.async.commit_group;" ::: "memory");
}
template <int N>
__device__ __forceinline__ void cp_wait() {
    asm volatile("cp.async.wait_group %0;" :: "n"(N) : "memory");
}
__device__ __forceinline__ void ldm4(uint32_t* r, uint32_t addr) {
    asm volatile("ldmatrix.sync.aligned.m8n8.x4.shared.b16 {%0,%1,%2,%3}, [%4];"
                 : "=r"(r[0]), "=r"(r[1]), "=r"(r[2]), "=r"(r[3]) : "r"(addr));
}
__device__ __forceinline__ void mma16816(float* c, const uint32_t* a, const uint32_t* b) {
    asm volatile("mma.sync.aligned.m16n8k16.row.col.f32.f16.f16.f32 "
                 "{%0,%1,%2,%3}, {%4,%5,%6,%7}, {%8,%9}, {%0,%1,%2,%3};"
                 : "+f"(c[0]), "+f"(c[1]), "+f"(c[2]), "+f"(c[3])
                 : "r"(a[0]), "r"(a[1]), "r"(a[2]), "r"(a[3]), "r"(b[0]), "r"(b[1]));
}
__device__ __forceinline__ uint32_t pack2(h16 a, h16 b) {
    uint16_t ua = *reinterpret_cast<uint16_t*>(&a);
    uint16_t ub = *reinterpret_cast<uint16_t*>(&b);
    return (uint32_t)ua | ((uint32_t)ub << 16);
}

// ---------------------------------------------------------------------------
// fp16 GEMM: C = scale*(A[M,K] x B[N,K]^T) (+bias). CTA tile 128x128, Kc=32.
// A/B smem row (64B): 32 fp16, XOR-((row>>1)&3)*16 swizzle.
// 8 warps in 4(m) x 2(n) grid, warp tile 32x64.
// OUT: 0 = fp32 C, 2 = fp16 Chi.
// ---------------------------------------------------------------------------
#define BM 128
#define BN 128
#define NSTAGE 6
#define A_BYTES 8192                     // 128 rows x 64B
#define B_BYTES 8192                     // 128 rows x 64B
#define STAGE_BYTES (A_BYTES + B_BYTES)  // 16384
#define SMEM_TOTAL (NSTAGE * STAGE_BYTES)  // 98304

template <bool HAS_BIAS, int OUT>
__global__ __launch_bounds__(256, 2) void gemm_fp16(
    const h16* __restrict__ Ah, const h16* __restrict__ Bh,
    const float* __restrict__ bias,
    float* __restrict__ C, h16* __restrict__ Chi,
    int K, int lda, int ldb, int ldc,
    long aBS, long bBS, long cBS, float scale)
{
    extern __shared__ char smem[];
    const uint32_t sb = smem_u32(smem);
    const int tid = threadIdx.x;
    const int lane = tid & 31;
    const int wid = tid >> 5;
    const int wm = wid & 3;       // m 32-quarter (0..3)
    const int wn = wid >> 2;      // n 64-half    (0..1)

    const long bm = (long)blockIdx.y * BM;
    const long bn = (long)blockIdx.x * BN;
    Ah += (long)blockIdx.z * aBS;
    Bh += (long)blockIdx.z * bBS;
    if (OUT == 0) C   += (long)blockIdx.z * cBS;
    else          Chi += (long)blockIdx.z * cBS;

    const int nchunk = K >> 5;

    // ---- cp.async assignments: A 2x16B/thread, B 2x16B/thread ----
    const h16* pA[2]; const h16* pB[2];
    uint32_t dAB[2];
#pragma unroll
    for (int i = 0; i < 2; i++) {
        int ch = tid + i * 256;          // 0..511
        int row = ch >> 2;               // 0..127
        int q = ch & 3;                  // 16B quarter in 64B row
        dAB[i] = (uint32_t)(row * 64) + ((uint32_t)(q * 16) ^ (((row >> 1) & 3) * 16));
        pA[i] = Ah + (size_t)(bm + row) * lda + q * 8;
        pB[i] = Bh + (size_t)(bn + row) * ldb + q * 8;
    }

    // ---- ldmatrix lane address components ----
    const int rA = (lane & 7) + ((lane >> 3) & 1) * 8;
    const uint32_t cA16 = ((lane >> 4) & 1) * 16;
    const int rB = (lane & 7) + ((lane >> 4) & 1) * 8;
    const uint32_t cB16 = ((lane >> 3) & 1) * 16;

    uint32_t aoff[2], axor[2];
#pragma unroll
    for (int mt = 0; mt < 2; mt++) {
        int arow = wm * 32 + mt * 16 + rA;
        aoff[mt] = arow * 64;
        axor[mt] = ((arow >> 1) & 3) * 16;
    }
    uint32_t boff[4], bxor[4];
#pragma unroll
    for (int t = 0; t < 4; t++) {
        int brow = wn * 64 + t * 16 + rB;
        boff[t] = brow * 64;
        bxor[t] = ((brow >> 1) & 3) * 16;
    }

    float acc[2][8][4];
#pragma unroll
    for (int mt = 0; mt < 2; mt++)
#pragma unroll
        for (int nt = 0; nt < 8; nt++)
#pragma unroll
            for (int r = 0; r < 4; r++) acc[mt][nt][r] = 0.f;

    // ---- prologue: stages 0..NSTAGE-2 in flight ----
#pragma unroll
    for (int st = 0; st < NSTAGE - 1; st++) {
        int k0 = st * 32;
        uint32_t base = sb + st * STAGE_BYTES;
        if (st < (K >> 5)) {
#pragma unroll
            for (int i = 0; i < 2; i++) cp16(base + dAB[i], pA[i] + k0);
#pragma unroll
            for (int i = 0; i < 2; i++) cp16(base + A_BYTES + dAB[i], pB[i] + k0);
        }
        cp_commit();
    }
    cp_wait<NSTAGE - 2>();
    __syncthreads();

    // ---- main loop: ONE barrier per chunk ----
    for (int kc = 0; kc < nchunk; kc++) {
        const uint32_t baseA = sb + (kc % NSTAGE) * STAGE_BYTES;
        const uint32_t baseB = baseA + A_BYTES;

        // prefetch chunk kc+NSTAGE-1 into the stage consumed at kc-1
        int next = kc + NSTAGE - 1;
        if (next < nchunk) {
            int k0 = next * 32;
            uint32_t nb = sb + (next % NSTAGE) * STAGE_BYTES;
#pragma unroll
            for (int i = 0; i < 2; i++) cp16(nb + dAB[i], pA[i] + k0);
#pragma unroll
            for (int i = 0; i < 2; i++) cp16(nb + A_BYTES + dAB[i], pB[i] + k0);
        }
        cp_commit();

        // compute current chunk: 2 k16 steps, 16 MMAs + 6 LDSM each
#pragma unroll
        for (int s = 0; s < 2; s++) {
            uint32_t bh[16];
#pragma unroll
            for (int t = 0; t < 4; t++) {
                uint32_t c = s * 32 + cB16;
                ldm4(&bh[t * 4], baseB + boff[t] + (c ^ bxor[t]));
            }
#pragma unroll
            for (int mt = 0; mt < 2; mt++) {
                uint32_t a[4];
                uint32_t cc = s * 32 + cA16;
                ldm4(a, baseA + aoff[mt] + (cc ^ axor[mt]));
#pragma unroll
                for (int nt = 0; nt < 8; nt++) mma16816(acc[mt][nt], a, &bh[nt * 2]);
            }
        }

        cp_wait<NSTAGE - 2>();   // chunk kc+1 resident
        __syncthreads();
    }

    // ---- epilogue ----
#pragma unroll
    for (int mt = 0; mt < 2; mt++) {
        long r0 = bm + wm * 32 + mt * 16 + (lane >> 2);
        long r1 = r0 + 8;
#pragma unroll
        for (int nt = 0; nt < 8; nt++) {
            long col = bn + wn * 64 + nt * 8 + (lane & 3) * 2;
            float b0v = 0.f, b1v = 0.f;
            if (HAS_BIAS) { b0v = bias[col]; b1v = bias[col + 1]; }
            float v00 = acc[mt][nt][0] * scale + b0v;
            float v01 = acc[mt][nt][1] * scale + b1v;
            float v10 = acc[mt][nt][2] * scale + b0v;
            float v11 = acc[mt][nt][3] * scale + b1v;
            if (OUT == 2) {
                *reinterpret_cast<uint32_t*>(&Chi[r0 * ldc + col]) =
                    pack2(__float2half(v00), __float2half(v01));
                *reinterpret_cast<uint32_t*>(&Chi[r1 * ldc + col]) =
                    pack2(__float2half(v10), __float2half(v11));
            } else {
                float2 u0 = make_float2(v00, v01);
                float2 u1 = make_float2(v10, v11);
                *reinterpret_cast<float2*>(&C[r0 * ldc + col]) = u0;
                *reinterpret_cast<float2*>(&C[r1 * ldc + col]) = u1;
            }
        }
    }
}

// ---------------------------------------------------------------------------
// fp32 -> fp16 conversion, merged over the three input tensors.
// Segments (in float4 units): X [0, n1), Wqkv [n1, n2), Wout [n2, n3).
// ---------------------------------------------------------------------------
__global__ __launch_bounds__(256) void split_all_kernel(
    const float* __restrict__ X, h16* __restrict__ Xh, int n1,
    const float* __restrict__ Wq, h16* __restrict__ Wqh, int n2,
    const float* __restrict__ Wo, h16* __restrict__ Woh, int n3)
{
    int i = blockIdx.x * blockDim.x + threadIdx.x;
    if (i >= n3) return;
    const float* src; h16* dst; int off;
    if (i < n1)      { src = X;  dst = Xh;  off = i; }
    else if (i < n2) { src = Wq; dst = Wqh; off = i - n1; }
    else             { src = Wo; dst = Woh; off = i - n2; }
    float4 v = reinterpret_cast<const float4*>(src)[off];
    reinterpret_cast<uint2*>(dst)[off] = make_uint2(
        pack2(__float2half(v.x), __float2half(v.y)),
        pack2(__float2half(v.z), __float2half(v.w)));
}

// ---------------------------------------------------------------------------
// V transpose (hi only): vt[b][e][s] = qkv[b*S+s][2E+e]
// ---------------------------------------------------------------------------
__global__ __launch_bounds__(256) void transpose_v_kernel(
    const h16* __restrict__ qh, h16* __restrict__ vth)
{
    __shared__ h16 th[32][33];
    const int b = blockIdx.z;
    const int e0 = blockIdx.x * 32;
    const int s0 = blockIdx.y * 32;
    const int tx = threadIdx.x & 31;
    const int ty = threadIdx.x >> 5;  // 0..7
#pragma unroll
    for (int i = 0; i < 4; i++) {
        int s = s0 + ty + i * 8;
        size_t idx = (size_t)(b * SEQ + s) * (3 * EMBED) + 2 * EMBED + e0 + tx;
        th[ty + i * 8][tx] = qh[idx];
    }
    __syncthreads();
#pragma unroll
    for (int i = 0; i < 4; i++) {
        int e = e0 + ty + i * 8;
        size_t o = (size_t)(b * EMBED + e) * SEQ + s0 + tx;
        vth[o] = th[tx][ty + i * 8];
    }
}

// ---------------------------------------------------------------------------
// Row softmax with mask, IN-PLACE on fp16 logits (one block per row).
// ---------------------------------------------------------------------------
__global__ __launch_bounds__(256) void softmax_kernel(
    h16* __restrict__ att, const int* __restrict__ mask)
{
    const size_t row = blockIdx.x;
    h16* a = att + row * SEQ;
    const int* m = mask + row * SEQ;
    const int tid = threadIdx.x;

    __shared__ float red_max[8];
    __shared__ float red_sum[8];

    float v[8];
    float mx = -INFINITY;
#pragma unroll
    for (int i = 0; i < 8; i++) {
        int idx = tid + i * 256;
        float x = __half2float(a[idx]);
        x = (m[idx] != 0) ? x : -INFINITY;
        v[i] = x;
        mx = fmaxf(mx, x);
    }
#pragma unroll
    for (int o = 16; o > 0; o >>= 1)
        mx = fmaxf(mx, __shfl_xor_sync(0xffffffffu, mx, o));
    if ((tid & 31) == 0) red_max[tid >> 5] = mx;
    __syncthreads();
    float bmax = red_max[0];
#pragma unroll
    for (int w = 1; w < 8; w++) bmax = fmaxf(bmax, red_max[w]);

    float s = 0.f;
#pragma unroll
    for (int i = 0; i < 8; i++) {
        v[i] = __expf(v[i] - bmax);
        s += v[i];
    }
#pragma unroll
    for (int o = 16; o > 0; o >>= 1)
        s += __shfl_xor_sync(0xffffffffu, s, o);
    if ((tid & 31) == 0) red_sum[tid >> 5] = s;
    __syncthreads();
    float total = 0.f;
#pragma unroll
    for (int w = 0; w < 8; w++) total += red_sum[w];

    float inv = 1.f / total;
#pragma unroll
    for (int i = 0; i < 8; i++) {
        int idx = tid + i * 256;
        a[idx] = __float2half(v[i] * inv);
    }
}

// ---------------------------------------------------------------------------
extern "C" void kernel_launch(void* const* d_in, const int* in_sizes, int n_in,
                              void* d_out, int out_size)
{
    const float* X    = (const float*)d_in[0];
    const int*   mask = (const int*)  d_in[1];
    const float* Wqkv = (const float*)d_in[2];
    const float* bqkv = (const float*)d_in[3];
    const float* Wout = (const float*)d_in[4];
    const float* bout = (const float*)d_in[5];
    float* out = (float*)d_out;

    h16 *Xhi, *Wqkvhi, *Wouthi, *qkvhi, *att, *vthi, *ctxhi;
    cudaGetSymbolAddress((void**)&Xhi, g_Xhi);
    cudaGetSymbolAddress((void**)&Wqkvhi, g_Wqkvhi);
    cudaGetSymbolAddress((void**)&Wouthi, g_Wouthi);
    cudaGetSymbolAddress((void**)&qkvhi, g_qkvhi);
    cudaGetSymbolAddress((void**)&att, g_att);
    cudaGetSymbolAddress((void**)&vthi, g_vthi);
    cudaGetSymbolAddress((void**)&ctxhi, g_ctxhi);

    // NOTE: attributes must be set on the EXACT instantiations launched below.
    cudaFuncSetAttribute(gemm_fp16<true, 2>,
                         cudaFuncAttributeMaxDynamicSharedMemorySize, SMEM_TOTAL);
    cudaFuncSetAttribute(gemm_fp16<false, 2>,
                         cudaFuncAttributeMaxDynamicSharedMemorySize, SMEM_TOTAL);
    cudaFuncSetAttribute(gemm_fp16<true, 0>,
                         cudaFuncAttributeMaxDynamicSharedMemorySize, SMEM_TOTAL);

    // 0) convert inputs to fp16 (single merged launch)
    {
        int n1 = ROWS * EMBED / 4;                 // X float4 count
        int n2 = n1 + 3 * EMBED * EMBED / 4;       // + Wqkv
        int n3 = n2 + EMBED * EMBED / 4;           // + Wout
        split_all_kernel<<<(n3 + 255) / 256, 256>>>(
            X, Xhi, n1, Wqkv, Wqkvhi, n2, Wout, Wouthi, n3);
    }

    // 1) qkv = X Wqkv^T + bqkv  (fp16 output)
    {
        dim3 grid(3 * EMBED / BN, ROWS / BM, 1);
        gemm_fp16<true, 2><<<grid, 256, SMEM_TOTAL>>>(
            Xhi, Wqkvhi, bqkv,
            nullptr, qkvhi,
            EMBED, EMBED, EMBED, 3 * EMBED,
            0, 0, 0, 1.0f);
    }
    // 2) vt = V^T
    {
        dim3 grid(EMBED / 32, SEQ / 32, BATCH);
        transpose_v_kernel<<<grid, 256>>>(qkvhi, vthi);
    }
    // 3) att = Q K^T / 32  (fp16 logits)
    {
        dim3 grid(SEQ / BN, SEQ / BM, BATCH);
        gemm_fp16<false, 2><<<grid, 256, SMEM_TOTAL>>>(
            qkvhi, qkvhi + EMBED, nullptr,
            nullptr, att,
            EMBED, 3 * EMBED, 3 * EMBED, SEQ,
            (long)SEQ * 3 * EMBED, (long)SEQ * 3 * EMBED, (long)SEQ * SEQ,
            1.0f / 32.0f);
    }
    // 4) softmax in-place on fp16 logits -> fp16 probs
    softmax_kernel<<<BATCH * SEQ, 256>>>(att, mask);

    // 5) ctx = p vt^T  (fp16 output)
    {
        dim3 grid(EMBED / BN, SEQ / BM, BATCH);
        gemm_fp16<false, 2><<<grid, 256, SMEM_TOTAL>>>(
            att, vthi, nullptr,
            nullptr, ctxhi,
            SEQ, SEQ, SEQ, EMBED,
            (long)SEQ * SEQ, (long)EMBED * SEQ, (long)SEQ * EMBED,
            1.0f);
    }
    // 6) out = ctx Wout^T + bout  (fp32)
    {
        dim3 grid(EMBED / BN, ROWS / BM, 1);
        gemm_fp16<true, 0><<<grid, 256, SMEM_TOTAL>>>(
            ctxhi, Wouthi, bout,
            out, nullptr,
            EMBED, EMBED, EMBED, EMBED,
            0, 0, 0, 1.0f);
    }
}